// round 11
// baseline (speedup 1.0000x reference)
#include <cuda_runtime.h>
#include <cuda_bf16.h>
#include <mma.h>
#include <cstdint>

using namespace nvcuda;

#define NN 100000
#define NE 1600000
#define DD 128
#define NG 64
#define NL 7
#define LEAKY 0.01f
#define BN_EPS 1e-5f

#define SCAN_BLK 256
#define SCAN_NB ((NN + SCAN_BLK - 1) / SCAN_BLK)   // 391
#define GATHER_BLOCKS 592                           // 4 per SM

// ---- wmma GEMM config ----
#define GT_GRID ((NN + 127) / 128)                  // 782
#define LDA 136                                      // bf16 leading dim (mult of 8, +skew)
#define LDB_F 136
// byte offsets in dynamic smem
#define SM_AHI 0
#define SM_ALO 34816
#define SM_BIAS 69632
#define GT_SMEM_BYTES 78336                          // 2 blocks/SM

// ---------------- scratch (static device globals; no allocation) ----------------
__device__ __align__(16) float  g_T[(size_t)NN * DD];       // GEMM output (messages source)
__device__ __align__(16) __nv_bfloat16 g_Ahi[(size_t)NN * DD];  // activated features split-hi
__device__ __align__(16) __nv_bfloat16 g_Alo[(size_t)NN * DD];  // activated features split-lo
__device__ int    g_cnt[NN];
__device__ int    g_rowptr[NN + 1];
__device__ int    g_bsum[SCAN_NB];
__device__ int    g_boff[SCAN_NB];
__device__ int    g_col[NE];
__device__ float  g_w[NE];
__device__ float  g_dinv[NN];
__device__ double g_sum[DD], g_sq[DD];
__device__ __align__(16) __nv_bfloat16 g_Whi[DD * DD];      // W^T split-hi, row-major [n][k]
__device__ __align__(16) __nv_bfloat16 g_Wlo[DD * DD];      // W^T split-lo
__device__ float  g_bf[DD];
__device__ float  g_a[DD], g_c[DD];
__device__ float  g_pool[NG * DD];
__device__ float  g_pcnt[NG];
__device__ int    g_is64_ei, g_is64_batch;

__device__ __forceinline__ float leaky_f(float v) { return v > 0.f ? v : LEAKY * v; }

__device__ __forceinline__ int load_idx(const void* p, long long i, int is64) {
    return is64 ? (int)((const long long*)p)[i] : ((const int*)p)[i];
}

// split fp32 -> (hi, lo) bf16, two values packed into u32 pairs (elem0 in low bits)
__device__ __forceinline__ void split2(float v0, float v1, uint32_t& hi, uint32_t& lo) {
    __nv_bfloat16 h0 = __float2bfloat16(v0);
    __nv_bfloat16 h1 = __float2bfloat16(v1);
    __nv_bfloat16 l0 = __float2bfloat16(v0 - __bfloat162float(h0));
    __nv_bfloat16 l1 = __float2bfloat16(v1 - __bfloat162float(h1));
    hi = ((uint32_t)__bfloat16_as_ushort(h1) << 16) | __bfloat16_as_ushort(h0);
    lo = ((uint32_t)__bfloat16_as_ushort(l1) << 16) | __bfloat16_as_ushort(l0);
}

// W^T split store: [n=j][k] row-major
__device__ __forceinline__ void store_wsplit(int k, int j, float v) {
    __nv_bfloat16 hi = __float2bfloat16(v);
    __nv_bfloat16 lo = __float2bfloat16(v - __bfloat162float(hi));
    g_Whi[j * 128 + k] = hi;
    g_Wlo[j * 128 + k] = lo;
}

// ---------------- dtype probe (warp-parallel) ----------------
#define PROBE_WORDS 2048
#define PROBE_THRESH 900
__global__ void detect_kernel(const int* __restrict__ ei_w,
                              const int* __restrict__ batch_w) {
    int lane = threadIdx.x & 31;
    int z = 0;
    for (int i = 1 + 2 * lane; i < PROBE_WORDS; i += 64)
        if (ei_w[i] == 0) z++;
    #pragma unroll
    for (int o = 16; o > 0; o >>= 1) z += __shfl_xor_sync(0xFFFFFFFFu, z, o);
    if (lane == 0) g_is64_ei = (z > PROBE_THRESH / 2) ? 1 : 0;
    int z2 = 0;
    const int base = NN / 2;
    for (int i = 1 + 2 * lane; i < PROBE_WORDS; i += 64)
        if (batch_w[base + i] == 0) z2++;
    #pragma unroll
    for (int o = 16; o > 0; o >>= 1) z2 += __shfl_xor_sync(0xFFFFFFFFu, z2, o);
    if (lane == 0) g_is64_batch = (z2 > PROBE_THRESH / 2) ? 1 : 0;
}

// ---------------- pre-pass kernels ----------------
__global__ void zero_kernel() {
    int idx = blockIdx.x * blockDim.x + threadIdx.x;
    if (idx < NN) g_cnt[idx] = 0;
    if (idx < NG * DD) g_pool[idx] = 0.f;
    if (idx < NG) g_pcnt[idx] = 0.f;
}

__global__ void hist_kernel(const void* __restrict__ ei) {
    int e = blockIdx.x * blockDim.x + threadIdx.x;
    if (e >= NE) return;
    int d = load_idx(ei, (long long)NE + e, g_is64_ei);
    atomicAdd(&g_cnt[d], 1);
}

__global__ void scan1_kernel() {
    __shared__ int wsum[8];
    int idx = blockIdx.x * SCAN_BLK + threadIdx.x;
    int lane = threadIdx.x & 31, wid = threadIdx.x >> 5;
    int v = (idx < NN) ? g_cnt[idx] : 0;
    int x = v;
    #pragma unroll
    for (int o = 1; o < 32; o <<= 1) {
        int y = __shfl_up_sync(0xFFFFFFFFu, x, o);
        if (lane >= o) x += y;
    }
    if (lane == 31) wsum[wid] = x;
    __syncthreads();
    if (wid == 0 && lane < 8) {
        int s = wsum[lane];
        #pragma unroll
        for (int o = 1; o < 8; o <<= 1) {
            int y = __shfl_up_sync(0xFFu, s, o);
            if (lane >= o) s += y;
        }
        wsum[lane] = s;
    }
    __syncthreads();
    int excl = x - v + (wid > 0 ? wsum[wid - 1] : 0);
    if (idx < NN) {
        g_rowptr[idx] = excl;
        g_dinv[idx] = rsqrtf((float)(v + 1));
    }
    if (threadIdx.x == SCAN_BLK - 1) g_bsum[blockIdx.x] = excl + v;
}

__global__ void scan2_kernel() {
    __shared__ int sh[SCAN_NB];
    int tid = threadIdx.x;
    if (tid < SCAN_NB) sh[tid] = g_bsum[tid];
    __syncthreads();
    for (int o = 1; o < SCAN_NB; o <<= 1) {
        int val = 0;
        if (tid < SCAN_NB && tid >= o) val = sh[tid - o];
        __syncthreads();
        if (tid < SCAN_NB) sh[tid] += val;
        __syncthreads();
    }
    if (tid < SCAN_NB) g_boff[tid] = (tid > 0) ? sh[tid - 1] : 0;
    if (tid == 0) g_rowptr[NN] = sh[SCAN_NB - 1];
}

__global__ void scan3_kernel() {
    int idx = blockIdx.x * SCAN_BLK + threadIdx.x;
    if (idx >= NN) return;
    int r = g_rowptr[idx] + g_boff[blockIdx.x];
    g_rowptr[idx] = r;
    g_cnt[idx] = r;
}

__global__ void fill_kernel(const void* __restrict__ ei) {
    int e = blockIdx.x * blockDim.x + threadIdx.x;
    if (e >= NE) return;
    int is64 = g_is64_ei;
    int s = load_idx(ei, e, is64);
    int d = load_idx(ei, (long long)NE + e, is64);
    int pos = atomicAdd(&g_cnt[d], 1);
    g_col[pos] = s;
    g_w[pos] = g_dinv[s] * g_dinv[d];
}

// layer-0 weight split (+ zero stat accumulators before the first gather)
__global__ void w0prep_kernel(const float* __restrict__ W0) {
    int j = threadIdx.x;
    g_sum[j] = 0.0; g_sq[j] = 0.0;
    for (int k = 0; k < 128; k++) store_wsplit(k, j, W0[k * 128 + j]);
}

// ---------------- split-bf16 wmma GEMM: T = A' @ W' + b ----------------
// A' (activated, split) comes pre-converted from gather (layers>=1) or is
// converted from x (layer 0). W fragments load straight from global (L1-resident).
__global__ __launch_bounds__(256) void gemm_tc(const float* __restrict__ x0,
                                               const float* __restrict__ b0,
                                               int layer) {
    extern __shared__ char smem[];
    const float* __restrict__ bias = layer ? g_bf : b0;
    int tid = threadIdx.x;
    int row0 = blockIdx.x * 128;

    __nv_bfloat16* sAhi = (__nv_bfloat16*)(smem + SM_AHI);
    __nv_bfloat16* sAlo = (__nv_bfloat16*)(smem + SM_ALO);
    float*         sBias = (float*)(smem + SM_BIAS);

    // bias broadcast tile: 16 rows x 128 cols, ld LDB_F
    for (int i = tid; i < 2048; i += 256) {
        int r = i >> 7, c = i & 127;
        sBias[r * LDB_F + c] = bias[c];
    }

    if (layer == 0) {
        // stage from fp32 x (no leaky on input features), split to bf16
        const float4* A4 = (const float4*)x0;
        uint32_t* ah = (uint32_t*)sAhi;
        uint32_t* al = (uint32_t*)sAlo;
        for (int i = tid; i < 4096; i += 256) {
            int r = i >> 5, q = i & 31;
            int row = row0 + r;
            float4 v = make_float4(0.f, 0.f, 0.f, 0.f);
            if (row < NN) v = A4[(size_t)row * 32 + q];
            uint32_t h0, l0, h1, l1;
            split2(v.x, v.y, h0, l0);
            split2(v.z, v.w, h1, l1);
            int b = r * (LDA / 2) + q * 2;
            ah[b] = h0; ah[b + 1] = h1;
            al[b] = l0; al[b + 1] = l1;
        }
    } else {
        // pure coalesced copy of pre-split features (4 bf16 per uint2)
        const uint2* gh = (const uint2*)g_Ahi;
        const uint2* gl = (const uint2*)g_Alo;
        uint2* sh2 = (uint2*)sAhi;
        uint2* sl2 = (uint2*)sAlo;
        const uint2 zz = make_uint2(0u, 0u);
        for (int i = tid; i < 8192; i += 256) {
            int half = i >> 12;           // 0: hi, 1: lo
            int j = i & 4095;
            int r = j >> 5, q = j & 31;   // row, uint2-within-row
            int row = row0 + r;
            uint2 v = zz;
            if (row < NN) v = half ? gl[(size_t)row * 32 + q] : gh[(size_t)row * 32 + q];
            if (half) sl2[r * (LDA / 4) + q] = v;
            else      sh2[r * (LDA / 4) + q] = v;
        }
    }
    __syncthreads();

    int warp = tid >> 5;
    int rowbase = (warp >> 1) * 32;      // 0,32,64,96
    int colbase = (warp & 1) * 64;       // 0,64

    wmma::fragment<wmma::accumulator, 16, 16, 16, float> acc[2][4];
    #pragma unroll
    for (int r = 0; r < 2; r++)
        #pragma unroll
        for (int c = 0; c < 4; c++)
            wmma::load_matrix_sync(acc[r][c], sBias + colbase + c * 16, LDB_F,
                                   wmma::mem_row_major);

    #pragma unroll
    for (int k0 = 0; k0 < 8; k0++) {
        wmma::fragment<wmma::matrix_a, 16, 16, 16, __nv_bfloat16, wmma::row_major> aH[2], aL[2];
        wmma::fragment<wmma::matrix_b, 16, 16, 16, __nv_bfloat16, wmma::col_major> bH[4], bL[4];
        #pragma unroll
        for (int r = 0; r < 2; r++) {
            wmma::load_matrix_sync(aH[r], sAhi + (rowbase + r * 16) * LDA + k0 * 16, LDA);
            wmma::load_matrix_sync(aL[r], sAlo + (rowbase + r * 16) * LDA + k0 * 16, LDA);
        }
        #pragma unroll
        for (int c = 0; c < 4; c++) {
            wmma::load_matrix_sync(bH[c], g_Whi + (colbase + c * 16) * 128 + k0 * 16, 128);
            wmma::load_matrix_sync(bL[c], g_Wlo + (colbase + c * 16) * 128 + k0 * 16, 128);
        }
        #pragma unroll
        for (int r = 0; r < 2; r++)
            #pragma unroll
            for (int c = 0; c < 4; c++) {
                wmma::mma_sync(acc[r][c], aH[r], bH[c], acc[r][c]);
                wmma::mma_sync(acc[r][c], aL[r], bH[c], acc[r][c]);
                wmma::mma_sync(acc[r][c], aH[r], bL[c], acc[r][c]);
            }
    }

    // store: NN % 16 == 0 so tile-granular guard is exact
    #pragma unroll
    for (int r = 0; r < 2; r++) {
        int rowt = row0 + rowbase + r * 16;
        if (rowt < NN) {
            #pragma unroll
            for (int c = 0; c < 4; c++)
                wmma::store_matrix_sync(g_T + (size_t)rowt * 128 + colbase + c * 16,
                                        acc[r][c], 128, wmma::mem_row_major);
        }
    }
}

// ---------------- persistent gather + fused stats + split-bf16 output ----------------
// AGG = normalized aggregate; stats over leaky(AGG); stores split(leaky(AGG)) into
// g_Ahi/g_Alo — the next GEMM's (and pool's) pre-activated, pre-converted input.
__global__ __launch_bounds__(256) void gather_kernel() {
    int lane = threadIdx.x & 31;
    int gwarp = blockIdx.x * 8 + (threadIdx.x >> 5);
    const int nwarps = GATHER_BLOCKS * 8;
    const float4* T4 = (const float4*)g_T;

    float4 ssum = make_float4(0.f, 0.f, 0.f, 0.f);
    float4 ssq  = make_float4(0.f, 0.f, 0.f, 0.f);

    for (int v = gwarp; v < NN; v += nwarps) {
        int beg = g_rowptr[v], end = g_rowptr[v + 1];
        float dv = g_dinv[v];
        float4 acc = T4[(size_t)v * 32 + lane];
        float s2 = dv * dv;
        acc.x *= s2; acc.y *= s2; acc.z *= s2; acc.w *= s2;
        int i = beg;
        for (; i + 4 <= end; i += 4) {
            int s0 = g_col[i], s1 = g_col[i + 1], s2i = g_col[i + 2], s3 = g_col[i + 3];
            float w0 = g_w[i], w1 = g_w[i + 1], w2 = g_w[i + 2], w3 = g_w[i + 3];
            float4 t0 = T4[(size_t)s0 * 32 + lane];
            float4 t1 = T4[(size_t)s1 * 32 + lane];
            float4 t2 = T4[(size_t)s2i * 32 + lane];
            float4 t3 = T4[(size_t)s3 * 32 + lane];
            acc.x += w0 * t0.x + w1 * t1.x + w2 * t2.x + w3 * t3.x;
            acc.y += w0 * t0.y + w1 * t1.y + w2 * t2.y + w3 * t3.y;
            acc.z += w0 * t0.z + w1 * t1.z + w2 * t2.z + w3 * t3.z;
            acc.w += w0 * t0.w + w1 * t1.w + w2 * t2.w + w3 * t3.w;
        }
        for (; i < end; i++) {
            int s = g_col[i]; float wt = g_w[i];
            float4 t = T4[(size_t)s * 32 + lane];
            acc.x += wt * t.x; acc.y += wt * t.y; acc.z += wt * t.z; acc.w += wt * t.w;
        }
        float lx = leaky_f(acc.x), ly = leaky_f(acc.y);
        float lz = leaky_f(acc.z), lw = leaky_f(acc.w);
        uint32_t h0, l0, h1, l1;
        split2(lx, ly, h0, l0);
        split2(lz, lw, h1, l1);
        ((uint2*)g_Ahi)[(size_t)v * 32 + lane] = make_uint2(h0, h1);
        ((uint2*)g_Alo)[(size_t)v * 32 + lane] = make_uint2(l0, l1);
        ssum.x += lx; ssum.y += ly; ssum.z += lz; ssum.w += lw;
        ssq.x += lx * lx; ssq.y += ly * ly; ssq.z += lz * lz; ssq.w += lw * lw;
    }

    __shared__ float bsum[128], bsq[128];
    if (threadIdx.x < 128) { bsum[threadIdx.x] = 0.f; bsq[threadIdx.x] = 0.f; }
    __syncthreads();
    int c0 = lane * 4;
    atomicAdd(&bsum[c0 + 0], ssum.x); atomicAdd(&bsq[c0 + 0], ssq.x);
    atomicAdd(&bsum[c0 + 1], ssum.y); atomicAdd(&bsq[c0 + 1], ssq.y);
    atomicAdd(&bsum[c0 + 2], ssum.z); atomicAdd(&bsq[c0 + 2], ssq.z);
    atomicAdd(&bsum[c0 + 3], ssum.w); atomicAdd(&bsq[c0 + 3], ssq.w);
    __syncthreads();
    if (threadIdx.x < 128) {
        atomicAdd(&g_sum[threadIdx.x], (double)bsum[threadIdx.x]);
        atomicAdd(&g_sq[threadIdx.x], (double)bsq[threadIdx.x]);
    }
}

// fold BN affine of layer i into next layer's split weights (or keep a,c for last)
__global__ void fold_kernel(const float* __restrict__ Wnext,
                            const float* __restrict__ bnext,
                            const float* __restrict__ gamma,
                            const float* __restrict__ beta,
                            int isLast) {
    int j = threadIdx.x;
    float mu = (float)(g_sum[j] / (double)NN);
    float var = (float)(g_sq[j] / (double)NN - (double)mu * (double)mu);
    var = fmaxf(var, 0.f);
    float a = gamma[j] * rsqrtf(var + BN_EPS);
    float cc = beta[j] - mu * a;
    __shared__ float sa[128], sc[128];
    sa[j] = a; sc[j] = cc;
    __syncthreads();
    g_sum[j] = 0.0; g_sq[j] = 0.0;   // reset for next layer's gather
    if (isLast) { g_a[j] = a; g_c[j] = cc; return; }
    float bacc = bnext[j];
    for (int k = 0; k < 128; k++) {
        float wraw = Wnext[k * 128 + j];          // raw weight
        store_wsplit(k, j, sa[k] * wraw);         // scaled weight into W'
        bacc += sc[k] * wraw;                     // bias uses RAW weight
    }
    g_bf[j] = bacc;
}

// run-length pooling over sorted batch ids (features arrive pre-activated, split)
__global__ void pool_kernel(const void* __restrict__ batch) {
    int c = threadIdx.x;
    int r0 = blockIdx.x * 128;
    int rend = min(r0 + 128, NN);
    int is64 = g_is64_batch;
    float a = g_a[c], cc = g_c[c];
    int curg = load_idx(batch, r0, is64);
    float acc = 0.f; int run = 0;
    for (int r = r0; r < rend; r++) {
        int g = load_idx(batch, r, is64);
        if (g != curg) {
            atomicAdd(&g_pool[curg * 128 + c], acc);
            if (c == 0) atomicAdd(&g_pcnt[curg], (float)run);
            acc = 0.f; run = 0; curg = g;
        }
        float v = __bfloat162float(g_Ahi[(size_t)r * 128 + c]) +
                  __bfloat162float(g_Alo[(size_t)r * 128 + c]);
        acc += v * a + cc;
        run++;
    }
    atomicAdd(&g_pool[curg * 128 + c], acc);
    if (c == 0) atomicAdd(&g_pcnt[curg], (float)run);
}

__global__ void final_kernel(float* __restrict__ out) {
    int idx = blockIdx.x * blockDim.x + threadIdx.x;
    if (idx < NG * DD) {
        int g = idx >> 7;
        out[idx] = g_pool[idx] / fmaxf(g_pcnt[g], 1.f);
    }
}

// ---------------- launch ----------------
extern "C" void kernel_launch(void* const* d_in, const int* in_sizes, int n_in,
                              void* d_out, int out_size) {
    const float* x = (const float*)d_in[0];
    const void* ei = d_in[1];
    const void* batch = d_in[2];
    const float* Ws = (const float*)d_in[3];
    const float* bs = (const float*)d_in[4];
    const float* gm = (const float*)d_in[5];
    const float* bt = (const float*)d_in[6];
    float* out = (float*)d_out;

    cudaFuncSetAttribute(gemm_tc, cudaFuncAttributeMaxDynamicSharedMemorySize,
                         GT_SMEM_BYTES);

    detect_kernel<<<1, 32>>>((const int*)ei, (const int*)batch);
    zero_kernel<<<(NN + 255) / 256, 256>>>();
    hist_kernel<<<(NE + 255) / 256, 256>>>(ei);
    scan1_kernel<<<SCAN_NB, SCAN_BLK>>>();
    scan2_kernel<<<1, 512>>>();
    scan3_kernel<<<SCAN_NB, SCAN_BLK>>>();
    fill_kernel<<<(NE + 255) / 256, 256>>>(ei);
    w0prep_kernel<<<1, 128>>>(Ws);

    for (int i = 0; i < NL; i++) {
        gemm_tc<<<GT_GRID, 256, GT_SMEM_BYTES>>>(x, bs, i);
        gather_kernel<<<GATHER_BLOCKS, 256>>>();
        int nxt = (i + 1 < NL) ? (i + 1) : 0;
        fold_kernel<<<1, 128>>>(Ws + (size_t)nxt * DD * DD, bs + (size_t)nxt * DD,
                                gm + (size_t)i * DD, bt + (size_t)i * DD,
                                (i == NL - 1) ? 1 : 0);
    }
    pool_kernel<<<(NN + 127) / 128, 128>>>(batch);
    final_kernel<<<(NG * DD + 255) / 256, 256>>>(out);
}

// round 12
// speedup vs baseline: 1.3597x; 1.3597x over previous
#include <cuda_runtime.h>

#define NN 100000
#define NE 1600000
#define DD 128
#define NG 64
#define NL 7
#define LEAKY 0.01f
#define BN_EPS 1e-5f

#define SCAN_BLK 256
#define SCAN_NB ((NN + SCAN_BLK - 1) / SCAN_BLK)   // 391
#define GATHER_BLOCKS 592                           // 4 per SM

// ---------------- scratch (static device globals; no allocation) ----------------
__device__ __align__(16) float  g_T[(size_t)NN * DD];     // GEMM output (messages source)
__device__ __align__(16) float  g_AGG[(size_t)NN * DD];   // aggregated (pre-activation)
__device__ int    g_cnt[NN];
__device__ int    g_rowptr[NN + 1];
__device__ int    g_bsum[SCAN_NB];
__device__ int    g_boff[SCAN_NB];
__device__ int    g_col[NE];
__device__ float  g_w[NE];
__device__ float  g_dinv[NN];
__device__ double g_sum[DD], g_sq[DD];
__device__ __align__(16) float  g_Wf[DD * DD];            // BN-folded weights for next layer
__device__ float  g_bf[DD];
__device__ float  g_a[DD], g_c[DD];
__device__ float  g_pool[NG * DD];
__device__ float  g_pcnt[NG];
__device__ int    g_is64_ei, g_is64_batch;

__device__ __forceinline__ float leaky_f(float v) { return v > 0.f ? v : LEAKY * v; }

__device__ __forceinline__ int load_idx(const void* p, long long i, int is64) {
    return is64 ? (int)((const long long*)p)[i] : ((const int*)p)[i];
}

// ---------------- dtype probe (warp-parallel) ----------------
#define PROBE_WORDS 2048
#define PROBE_THRESH 900
__global__ void detect_kernel(const int* __restrict__ ei_w,
                              const int* __restrict__ batch_w) {
    int lane = threadIdx.x & 31;
    int z = 0;
    for (int i = 1 + 2 * lane; i < PROBE_WORDS; i += 64)
        if (ei_w[i] == 0) z++;
    #pragma unroll
    for (int o = 16; o > 0; o >>= 1) z += __shfl_xor_sync(0xFFFFFFFFu, z, o);
    if (lane == 0) g_is64_ei = (z > PROBE_THRESH / 2) ? 1 : 0;
    int z2 = 0;
    const int base = NN / 2;
    for (int i = 1 + 2 * lane; i < PROBE_WORDS; i += 64)
        if (batch_w[base + i] == 0) z2++;
    #pragma unroll
    for (int o = 16; o > 0; o >>= 1) z2 += __shfl_xor_sync(0xFFFFFFFFu, z2, o);
    if (lane == 0) g_is64_batch = (z2 > PROBE_THRESH / 2) ? 1 : 0;
}

// ---------------- pre-pass kernels ----------------
__global__ void zero_kernel() {
    int idx = blockIdx.x * blockDim.x + threadIdx.x;
    if (idx < NN) g_cnt[idx] = 0;
    if (idx < NG * DD) g_pool[idx] = 0.f;
    if (idx < NG) g_pcnt[idx] = 0.f;
}

__global__ void hist_kernel(const void* __restrict__ ei) {
    int e = blockIdx.x * blockDim.x + threadIdx.x;
    if (e >= NE) return;
    int d = load_idx(ei, (long long)NE + e, g_is64_ei);
    atomicAdd(&g_cnt[d], 1);
}

__global__ void scan1_kernel() {
    __shared__ int wsum[8];
    int idx = blockIdx.x * SCAN_BLK + threadIdx.x;
    int lane = threadIdx.x & 31, wid = threadIdx.x >> 5;
    int v = (idx < NN) ? g_cnt[idx] : 0;
    int x = v;
    #pragma unroll
    for (int o = 1; o < 32; o <<= 1) {
        int y = __shfl_up_sync(0xFFFFFFFFu, x, o);
        if (lane >= o) x += y;
    }
    if (lane == 31) wsum[wid] = x;
    __syncthreads();
    if (wid == 0 && lane < 8) {
        int s = wsum[lane];
        #pragma unroll
        for (int o = 1; o < 8; o <<= 1) {
            int y = __shfl_up_sync(0xFFu, s, o);
            if (lane >= o) s += y;
        }
        wsum[lane] = s;
    }
    __syncthreads();
    int excl = x - v + (wid > 0 ? wsum[wid - 1] : 0);
    if (idx < NN) {
        g_rowptr[idx] = excl;
        g_dinv[idx] = rsqrtf((float)(v + 1));
    }
    if (threadIdx.x == SCAN_BLK - 1) g_bsum[blockIdx.x] = excl + v;
}

__global__ void scan2_kernel() {
    __shared__ int sh[SCAN_NB];
    int tid = threadIdx.x;
    if (tid < SCAN_NB) sh[tid] = g_bsum[tid];
    __syncthreads();
    for (int o = 1; o < SCAN_NB; o <<= 1) {
        int val = 0;
        if (tid < SCAN_NB && tid >= o) val = sh[tid - o];
        __syncthreads();
        if (tid < SCAN_NB) sh[tid] += val;
        __syncthreads();
    }
    if (tid < SCAN_NB) g_boff[tid] = (tid > 0) ? sh[tid - 1] : 0;
    if (tid == 0) g_rowptr[NN] = sh[SCAN_NB - 1];
}

__global__ void scan3_kernel() {
    int idx = blockIdx.x * SCAN_BLK + threadIdx.x;
    if (idx >= NN) return;
    int r = g_rowptr[idx] + g_boff[blockIdx.x];
    g_rowptr[idx] = r;
    g_cnt[idx] = r;
}

__global__ void fill_kernel(const void* __restrict__ ei) {
    int e = blockIdx.x * blockDim.x + threadIdx.x;
    if (e >= NE) return;
    int is64 = g_is64_ei;
    int s = load_idx(ei, e, is64);
    int d = load_idx(ei, (long long)NE + e, is64);
    int pos = atomicAdd(&g_cnt[d], 1);
    g_col[pos] = s;
    g_w[pos] = g_dinv[s] * g_dinv[d];
}

// ---------------- per-layer kernels ----------------
// T = f(A) @ W + b  (f = leaky for layer>0; BN affine pre-folded into W,b)
// Inner product uses packed fp32x2 FMAs (fma.rn.f32x2, sm_100+): 2x fma-pipe tput,
// full fp32 precision. Also zeroes the channel-stat accumulators (block 0).
__global__ __launch_bounds__(256) void gemm_kernel(const float* __restrict__ x0,
                                                   const float* __restrict__ W0,
                                                   const float* __restrict__ b0,
                                                   int layer) {
    const float* __restrict__ A    = layer ? g_AGG : x0;
    const float* __restrict__ W    = layer ? g_Wf  : W0;
    const float* __restrict__ bias = layer ? g_bf  : b0;

    __shared__ __align__(16) float sA[16][132];
    __shared__ __align__(16) float sW[16][128];
    __shared__ float sB[128];
    int tid = threadIdx.x;
    if (blockIdx.x == 0 && tid < 128) { g_sum[tid] = 0.0; g_sq[tid] = 0.0; }
    if (tid < 128) sB[tid] = bias[tid];

    int row0 = blockIdx.x * 128;
    int tx = tid & 15, ty = tid >> 4;

    unsigned long long acc2[8][4];          // packed fp32 pairs (cols 2j, 2j+1)
    #pragma unroll
    for (int i = 0; i < 8; i++)
        #pragma unroll
        for (int j = 0; j < 4; j++) acc2[i][j] = 0ULL;

    const float4* W4 = (const float4*)W;
    for (int k0 = 0; k0 < 128; k0 += 16) {
        #pragma unroll
        for (int t = 0; t < 2; t++) {
            int idx = tid + t * 256;
            ((float4*)&sW[0][0])[idx] = W4[k0 * 32 + idx];
        }
        #pragma unroll
        for (int t = 0; t < 2; t++) {
            int idx = tid + t * 256;
            int r = idx >> 2, q = idx & 3;
            int row = row0 + r;
            float4 v = make_float4(0.f, 0.f, 0.f, 0.f);
            if (row < NN) v = *((const float4*)(A + (size_t)row * 128 + k0 + q * 4));
            if (layer) {
                v.x = leaky_f(v.x); v.y = leaky_f(v.y);
                v.z = leaky_f(v.z); v.w = leaky_f(v.w);
            }
            sA[q * 4 + 0][r] = v.x; sA[q * 4 + 1][r] = v.y;
            sA[q * 4 + 2][r] = v.z; sA[q * 4 + 3][r] = v.w;
        }
        __syncthreads();
        #pragma unroll
        for (int kk = 0; kk < 16; kk++) {
            float a[8];
            *(float4*)&a[0] = *(const float4*)&sA[kk][ty * 8];
            *(float4*)&a[4] = *(const float4*)&sA[kk][ty * 8 + 4];
            float4 b0v = *(const float4*)&sW[kk][tx * 8];
            float4 b1v = *(const float4*)&sW[kk][tx * 8 + 4];
            unsigned long long bb[4];
            asm("mov.b64 %0, {%1, %2};" : "=l"(bb[0]) : "f"(b0v.x), "f"(b0v.y));
            asm("mov.b64 %0, {%1, %2};" : "=l"(bb[1]) : "f"(b0v.z), "f"(b0v.w));
            asm("mov.b64 %0, {%1, %2};" : "=l"(bb[2]) : "f"(b1v.x), "f"(b1v.y));
            asm("mov.b64 %0, {%1, %2};" : "=l"(bb[3]) : "f"(b1v.z), "f"(b1v.w));
            #pragma unroll
            for (int i = 0; i < 8; i++) {
                unsigned long long aa;
                asm("mov.b64 %0, {%1, %1};" : "=l"(aa) : "f"(a[i]));
                #pragma unroll
                for (int j = 0; j < 4; j++)
                    asm("fma.rn.f32x2 %0, %1, %2, %0;"
                        : "+l"(acc2[i][j]) : "l"(aa), "l"(bb[j]));
            }
        }
        __syncthreads();
    }
    #pragma unroll
    for (int i = 0; i < 8; i++) {
        int row = row0 + ty * 8 + i;
        if (row < NN) {
            float c[8];
            #pragma unroll
            for (int j = 0; j < 4; j++)
                asm("mov.b64 {%0, %1}, %2;"
                    : "=f"(c[2 * j]), "=f"(c[2 * j + 1]) : "l"(acc2[i][j]));
            float4 o0 = make_float4(c[0] + sB[tx * 8 + 0], c[1] + sB[tx * 8 + 1],
                                    c[2] + sB[tx * 8 + 2], c[3] + sB[tx * 8 + 3]);
            float4 o1 = make_float4(c[4] + sB[tx * 8 + 4], c[5] + sB[tx * 8 + 5],
                                    c[6] + sB[tx * 8 + 6], c[7] + sB[tx * 8 + 7]);
            *((float4*)(g_T + (size_t)row * 128 + tx * 8))     = o0;
            *((float4*)(g_T + (size_t)row * 128 + tx * 8 + 4)) = o1;
        }
    }
}

// ---------------- persistent gather + fused channel stats ----------------
__global__ __launch_bounds__(256) void gather_kernel() {
    int lane = threadIdx.x & 31;
    int gwarp = blockIdx.x * 8 + (threadIdx.x >> 5);
    const int nwarps = GATHER_BLOCKS * 8;
    const float4* T4 = (const float4*)g_T;

    float4 ssum = make_float4(0.f, 0.f, 0.f, 0.f);
    float4 ssq  = make_float4(0.f, 0.f, 0.f, 0.f);

    for (int v = gwarp; v < NN; v += nwarps) {
        int beg = g_rowptr[v], end = g_rowptr[v + 1];
        float dv = g_dinv[v];
        float4 acc = T4[(size_t)v * 32 + lane];
        float s2 = dv * dv;
        acc.x *= s2; acc.y *= s2; acc.z *= s2; acc.w *= s2;
        int i = beg;
        for (; i + 4 <= end; i += 4) {
            int s0 = g_col[i], s1 = g_col[i + 1], s2i = g_col[i + 2], s3 = g_col[i + 3];
            float w0 = g_w[i], w1 = g_w[i + 1], w2 = g_w[i + 2], w3 = g_w[i + 3];
            float4 t0 = T4[(size_t)s0 * 32 + lane];
            float4 t1 = T4[(size_t)s1 * 32 + lane];
            float4 t2 = T4[(size_t)s2i * 32 + lane];
            float4 t3 = T4[(size_t)s3 * 32 + lane];
            acc.x += w0 * t0.x + w1 * t1.x + w2 * t2.x + w3 * t3.x;
            acc.y += w0 * t0.y + w1 * t1.y + w2 * t2.y + w3 * t3.y;
            acc.z += w0 * t0.z + w1 * t1.z + w2 * t2.z + w3 * t3.z;
            acc.w += w0 * t0.w + w1 * t1.w + w2 * t2.w + w3 * t3.w;
        }
        for (; i < end; i++) {
            int s = g_col[i]; float wt = g_w[i];
            float4 t = T4[(size_t)s * 32 + lane];
            acc.x += wt * t.x; acc.y += wt * t.y; acc.z += wt * t.z; acc.w += wt * t.w;
        }
        ((float4*)g_AGG)[(size_t)v * 32 + lane] = acc;
        float lx = leaky_f(acc.x), ly = leaky_f(acc.y);
        float lz = leaky_f(acc.z), lw = leaky_f(acc.w);
        ssum.x += lx; ssum.y += ly; ssum.z += lz; ssum.w += lw;
        ssq.x += lx * lx; ssq.y += ly * ly; ssq.z += lz * lz; ssq.w += lw * lw;
    }

    __shared__ float bsum[128], bsq[128];
    if (threadIdx.x < 128) { bsum[threadIdx.x] = 0.f; bsq[threadIdx.x] = 0.f; }
    __syncthreads();
    int c0 = lane * 4;
    atomicAdd(&bsum[c0 + 0], ssum.x); atomicAdd(&bsq[c0 + 0], ssq.x);
    atomicAdd(&bsum[c0 + 1], ssum.y); atomicAdd(&bsq[c0 + 1], ssq.y);
    atomicAdd(&bsum[c0 + 2], ssum.z); atomicAdd(&bsq[c0 + 2], ssq.z);
    atomicAdd(&bsum[c0 + 3], ssum.w); atomicAdd(&bsq[c0 + 3], ssq.w);
    __syncthreads();
    if (threadIdx.x < 128) {
        atomicAdd(&g_sum[threadIdx.x], (double)bsum[threadIdx.x]);
        atomicAdd(&g_sq[threadIdx.x], (double)bsq[threadIdx.x]);
    }
}

// fold BN affine of layer i into next layer's W,b (or keep a,c for last layer)
__global__ void fold_kernel(const float* __restrict__ Wnext,
                            const float* __restrict__ bnext,
                            const float* __restrict__ gamma,
                            const float* __restrict__ beta,
                            int isLast) {
    int j = threadIdx.x;
    float mu = (float)(g_sum[j] / (double)NN);
    float var = (float)(g_sq[j] / (double)NN - (double)mu * (double)mu);
    var = fmaxf(var, 0.f);
    float a = gamma[j] * rsqrtf(var + BN_EPS);
    float cc = beta[j] - mu * a;
    __shared__ float sa[128], sc[128];
    sa[j] = a; sc[j] = cc;
    __syncthreads();
    g_sum[j] = 0.0; g_sq[j] = 0.0;   // reset for next layer's gather
    if (isLast) { g_a[j] = a; g_c[j] = cc; return; }
    float bacc = bnext[j];
    for (int k = 0; k < 128; k++) {
        float wkj = Wnext[k * 128 + j];
        g_Wf[k * 128 + j] = sa[k] * wkj;
        bacc += sc[k] * wkj;          // bias uses RAW weight
    }
    g_bf[j] = bacc;
}

// run-length pooling over sorted batch ids
__global__ void pool_kernel(const void* __restrict__ batch) {
    int c = threadIdx.x;
    int r0 = blockIdx.x * 128;
    int rend = min(r0 + 128, NN);
    int is64 = g_is64_batch;
    float a = g_a[c], cc = g_c[c];
    int curg = load_idx(batch, r0, is64);
    float acc = 0.f; int run = 0;
    for (int r = r0; r < rend; r++) {
        int g = load_idx(batch, r, is64);
        if (g != curg) {
            atomicAdd(&g_pool[curg * 128 + c], acc);
            if (c == 0) atomicAdd(&g_pcnt[curg], (float)run);
            acc = 0.f; run = 0; curg = g;
        }
        float v = leaky_f(g_AGG[(size_t)r * 128 + c]);
        acc += v * a + cc;
        run++;
    }
    atomicAdd(&g_pool[curg * 128 + c], acc);
    if (c == 0) atomicAdd(&g_pcnt[curg], (float)run);
}

__global__ void final_kernel(float* __restrict__ out) {
    int idx = blockIdx.x * blockDim.x + threadIdx.x;
    if (idx < NG * DD) {
        int g = idx >> 7;
        out[idx] = g_pool[idx] / fmaxf(g_pcnt[g], 1.f);
    }
}

// ---------------- launch ----------------
extern "C" void kernel_launch(void* const* d_in, const int* in_sizes, int n_in,
                              void* d_out, int out_size) {
    const float* x = (const float*)d_in[0];
    const void* ei = d_in[1];
    const void* batch = d_in[2];
    const float* Ws = (const float*)d_in[3];
    const float* bs = (const float*)d_in[4];
    const float* gm = (const float*)d_in[5];
    const float* bt = (const float*)d_in[6];
    float* out = (float*)d_out;

    detect_kernel<<<1, 32>>>((const int*)ei, (const int*)batch);
    zero_kernel<<<(NN + 255) / 256, 256>>>();
    hist_kernel<<<(NE + 255) / 256, 256>>>(ei);
    scan1_kernel<<<SCAN_NB, SCAN_BLK>>>();
    scan2_kernel<<<1, 512>>>();
    scan3_kernel<<<SCAN_NB, SCAN_BLK>>>();
    fill_kernel<<<(NE + 255) / 256, 256>>>(ei);

    for (int i = 0; i < NL; i++) {
        gemm_kernel<<<(NN + 127) / 128, 256>>>(x, Ws + (size_t)i * DD * DD,
                                               bs + (size_t)i * DD, i);
        gather_kernel<<<GATHER_BLOCKS, 256>>>();
        int nxt = (i + 1 < NL) ? (i + 1) : 0;
        fold_kernel<<<1, 128>>>(Ws + (size_t)nxt * DD * DD, bs + (size_t)nxt * DD,
                                gm + (size_t)i * DD, bt + (size_t)i * DD,
                                (i == NL - 1) ? 1 : 0);
    }
    pool_kernel<<<(NN + 127) / 128, 128>>>(batch);
    final_kernel<<<(NG * DD + 255) / 256, 256>>>(out);
}